// round 1
// baseline (speedup 1.0000x reference)
#include <cuda_runtime.h>
#include <cstdint>
#include <cstddef>

#define BB 64
#define TT 512
#define EE 300
#define HH 1024
#define GG 3072   // 3*HH
#define OO 5

#define NB 128    // blocks in persistent recurrent kernel (<= 148 SMs)
#define JPB 8     // HH / NB hidden units per block
#define KC 64     // k-chunk staged in smem

// ---------------- device scratch (no allocations allowed) ----------------
__device__ float g_gx[(size_t)TT * GG * BB];   // [t][g][b]  (402 MB)
__device__ float g_WT[EE * GG];                // W_ih transposed: [e][g]
__device__ float g_h[2][HH * BB];              // hidden double buffer, [j][b]
__device__ unsigned g_arrive;                  // grid barrier counter

// ---------------- tiny helpers ----------------
__global__ void k_reset() { g_arrive = 0u; }

__global__ void k_transpose(const float* __restrict__ Wih) {
    int i = blockIdx.x * blockDim.x + threadIdx.x;  // over e*GG + g
    if (i < EE * GG) {
        int e = i / GG, g = i - e * GG;
        g_WT[i] = Wih[(size_t)g * EE + e];
    }
}

// ---------------- kernel A: gx[t][g][b] = b_ih[g] + sum_e W_ih[g,e]*emb[x[b,t],e] ----------------
// one block per t; smem: embS[EE][BB] + Wt[EE][64]; micro-tile 2b x 8g per thread.
__global__ void __launch_bounds__(256) k_gx(const int* __restrict__ x,
                                            const float* __restrict__ emb,
                                            const float* __restrict__ bih) {
    extern __shared__ float sm[];
    float* embS = sm;            // [e][b]
    float* Wt   = sm + EE * BB;  // [e][64] current g-tile

    const int t   = blockIdx.x;
    const int tid = threadIdx.x;

    // gather embeddings for the 64 batch rows at this t
    for (int i = tid; i < BB * EE; i += 256) {
        int b = i / EE, e = i - b * EE;
        embS[e * BB + b] = emb[(size_t)x[b * TT + t] * EE + e];
    }

    const int bg = tid & 31;   // b-pair index (covers 64 b as float2)
    const int gy = tid >> 5;   // 0..7, each owns 8 g's per tile

    for (int gt = 0; gt < GG / 64; gt++) {
        __syncthreads();  // embS ready (iter 0) / previous tile reads done
        for (int i = tid; i < EE * 64; i += 256) {
            int e = i >> 6, g = i & 63;
            Wt[i] = g_WT[e * GG + gt * 64 + g];
        }
        __syncthreads();

        float a0[8], a1[8];
#pragma unroll
        for (int j = 0; j < 8; j++) { a0[j] = 0.f; a1[j] = 0.f; }

        for (int e = 0; e < EE; e++) {
            float2 eb = *(float2*)&embS[e * BB + bg * 2];
            const float* wr = &Wt[e * 64 + gy * 8];
#pragma unroll
            for (int j = 0; j < 8; j++) {
                float w = wr[j];
                a0[j] += eb.x * w;
                a1[j] += eb.y * w;
            }
        }
#pragma unroll
        for (int j = 0; j < 8; j++) {
            int g = gt * 64 + gy * 8 + j;
            float bi = bih[g];
            float2 o; o.x = a0[j] + bi; o.y = a1[j] + bi;
            *(float2*)&g_gx[((size_t)t * GG + g) * BB + bg * 2] = o;
        }
    }
}

// ---------------- grid-wide spin barrier (monotonic counter) ----------------
__device__ __forceinline__ void gridbar(unsigned target) {
    __threadfence();          // release h writes (already at L2 via stcg)
    __syncthreads();
    if (threadIdx.x == 0) {
        atomicAdd(&g_arrive, 1u);
        unsigned v;
        do {
            asm volatile("ld.global.acquire.gpu.u32 %0, [%1];"
                         : "=r"(v) : "l"(&g_arrive) : "memory");
        } while (v < target);
    }
    __syncthreads();
}

__device__ __forceinline__ float sigf(float v) { return 1.0f / (1.0f + expf(-v)); }

// ---------------- kernel B: persistent GRU recurrence ----------------
// block i owns hidden units j in [i*JPB, i*JPB+JPB). W slice cached in smem for all 512 steps.
// threads: 128 = 32 b-pairs (bg) x 4 j-pairs (jg). 12 accumulators (3 gates x 2j x 2b).
__global__ void __launch_bounds__(128, 1) k_rnn(const float* __restrict__ Whh,
                                                const float* __restrict__ bhh) {
    extern __shared__ float sm[];
    float* Wsm = sm;                  // [3][HH][JPB]
    float* hs  = sm + 3 * HH * JPB;   // [KC][BB]

    const int tid = threadIdx.x;
    const int bg  = tid & 31;
    const int jg  = tid >> 5;         // 0..3
    const int jbase = blockIdx.x * JPB;

    // load W_hh slice: Wsm[gate][k][jl] = Whh[(gate*HH + jbase + jl)*HH + k]
    for (int i = tid; i < 3 * HH * JPB; i += 128) {
        int k    = i & (HH - 1);
        int jl   = (i >> 10) & 7;
        int gate = i >> 13;
        Wsm[gate * (HH * JPB) + k * JPB + jl] =
            Whh[((size_t)(gate * HH + jbase + jl)) * HH + k];
    }

    const int j0 = jbase + jg * 2, j1 = j0 + 1;
    const float br0 = bhh[j0],          br1 = bhh[j1];
    const float bz0 = bhh[HH + j0],     bz1 = bhh[HH + j1];
    const float bn0 = bhh[2 * HH + j0], bn1 = bhh[2 * HH + j1];

    // zero h buffer 0 (our slice) — must happen every launch (graph replays)
    for (int i = tid; i < JPB * BB; i += 128)
        __stcg(&g_h[0][jbase * BB + i], 0.f);

    unsigned tgt = NB;       // barrier phase 1: all slices zeroed
    gridbar(tgt);

    for (int t = 0; t < TT; t++) {
        const float* hin  = g_h[t & 1];
        float*       hout = g_h[(t + 1) & 1];

        float acc[3][2][2];
#pragma unroll
        for (int g3 = 0; g3 < 3; g3++)
#pragma unroll
            for (int a = 0; a < 2; a++)
#pragma unroll
                for (int c = 0; c < 2; c++) acc[g3][a][c] = 0.f;

        for (int kc = 0; kc < HH; kc += KC) {
            __syncthreads();
            // stage h chunk [KC][BB] via L2 (other SMs wrote it; L1 is stale)
            for (int i = tid * 4; i < KC * BB; i += 128 * 4) {
                float4 v = __ldcg((const float4*)&hin[kc * BB + i]);
                *(float4*)&hs[i] = v;
            }
            __syncthreads();
#pragma unroll 8
            for (int k2 = 0; k2 < KC; k2++) {
                int k = kc + k2;
                float2 h2 = *(float2*)&hs[k2 * BB + bg * 2];
                float2 wr = *(float2*)&Wsm[0 * (HH * JPB) + k * JPB + jg * 2];
                float2 wz = *(float2*)&Wsm[1 * (HH * JPB) + k * JPB + jg * 2];
                float2 wn = *(float2*)&Wsm[2 * (HH * JPB) + k * JPB + jg * 2];
                acc[0][0][0] += wr.x * h2.x; acc[0][0][1] += wr.x * h2.y;
                acc[0][1][0] += wr.y * h2.x; acc[0][1][1] += wr.y * h2.y;
                acc[1][0][0] += wz.x * h2.x; acc[1][0][1] += wz.x * h2.y;
                acc[1][1][0] += wz.y * h2.x; acc[1][1][1] += wz.y * h2.y;
                acc[2][0][0] += wn.x * h2.x; acc[2][0][1] += wn.x * h2.y;
                acc[2][1][0] += wn.y * h2.x; acc[2][1][1] += wn.y * h2.y;
            }
        }

        // gates + state update for (j0,j1) x (b0,b1)
        const float* gxt = g_gx + (size_t)t * GG * BB;
        float2 xr0 = *(const float2*)&gxt[(0 * HH + j0) * BB + bg * 2];
        float2 xr1 = *(const float2*)&gxt[(0 * HH + j1) * BB + bg * 2];
        float2 xz0 = *(const float2*)&gxt[(1 * HH + j0) * BB + bg * 2];
        float2 xz1 = *(const float2*)&gxt[(1 * HH + j1) * BB + bg * 2];
        float2 xn0 = *(const float2*)&gxt[(2 * HH + j0) * BB + bg * 2];
        float2 xn1 = *(const float2*)&gxt[(2 * HH + j1) * BB + bg * 2];
        float2 h0 = __ldcg((const float2*)&hin[j0 * BB + bg * 2]);
        float2 h1 = __ldcg((const float2*)&hin[j1 * BB + bg * 2]);

        float r, z, n;
        float2 o0, o1;
        // j0, b0
        r = sigf(xr0.x + acc[0][0][0] + br0);
        z = sigf(xz0.x + acc[1][0][0] + bz0);
        n = tanhf(xn0.x + r * (acc[2][0][0] + bn0));
        o0.x = (1.f - z) * n + z * h0.x;
        // j0, b1
        r = sigf(xr0.y + acc[0][0][1] + br0);
        z = sigf(xz0.y + acc[1][0][1] + bz0);
        n = tanhf(xn0.y + r * (acc[2][0][1] + bn0));
        o0.y = (1.f - z) * n + z * h0.y;
        // j1, b0
        r = sigf(xr1.x + acc[0][1][0] + br1);
        z = sigf(xz1.x + acc[1][1][0] + bz1);
        n = tanhf(xn1.x + r * (acc[2][1][0] + bn1));
        o1.x = (1.f - z) * n + z * h1.x;
        // j1, b1
        r = sigf(xr1.y + acc[0][1][1] + br1);
        z = sigf(xz1.y + acc[1][1][1] + bz1);
        n = tanhf(xn1.y + r * (acc[2][1][1] + bn1));
        o1.y = (1.f - z) * n + z * h1.y;

        __stcg((float2*)&hout[j0 * BB + bg * 2], o0);
        __stcg((float2*)&hout[j1 * BB + bg * 2], o1);

        tgt += NB;
        gridbar(tgt);
    }
}

// ---------------- kernel C: out[b][o] = h_last[:,b] . W_fc[o,:] + b_fc[o] ----------------
__global__ void k_fc(const float* __restrict__ Wfc, const float* __restrict__ bfc,
                     float* __restrict__ out) {
    int tid = threadIdx.x;
    if (tid >= BB * OO) return;
    int b = tid & 63, o = tid >> 6;
    const float* h = g_h[0];   // TT even -> final state in buffer 0
    float a0 = 0.f, a1 = 0.f, a2 = 0.f, a3 = 0.f;
    for (int j = 0; j < HH; j += 4) {
        a0 += h[(j + 0) * BB + b] * Wfc[o * HH + j + 0];
        a1 += h[(j + 1) * BB + b] * Wfc[o * HH + j + 1];
        a2 += h[(j + 2) * BB + b] * Wfc[o * HH + j + 2];
        a3 += h[(j + 3) * BB + b] * Wfc[o * HH + j + 3];
    }
    out[b * OO + o] = a0 + a1 + a2 + a3 + bfc[o];
}

// ---------------- entry ----------------
extern "C" void kernel_launch(void* const* d_in, const int* in_sizes, int n_in,
                              void* d_out, int out_size) {
    const int*   x   = (const int*)d_in[0];
    const float* emb = (const float*)d_in[1];
    const float* Wih = (const float*)d_in[2];
    const float* Whh = (const float*)d_in[3];
    const float* bih = (const float*)d_in[4];
    const float* bhh = (const float*)d_in[5];
    const float* Wfc = (const float*)d_in[6];
    const float* bfc = (const float*)d_in[7];
    float* out = (float*)d_out;

    const int smemA = 2 * EE * BB * (int)sizeof(float);               // 153.6 KB
    const int smemB = (3 * HH * JPB + KC * BB) * (int)sizeof(float);  // 114.7 KB
    cudaFuncSetAttribute(k_gx,  cudaFuncAttributeMaxDynamicSharedMemorySize, smemA);
    cudaFuncSetAttribute(k_rnn, cudaFuncAttributeMaxDynamicSharedMemorySize, smemB);

    k_reset<<<1, 1>>>();
    k_transpose<<<(EE * GG + 255) / 256, 256>>>(Wih);
    k_gx<<<TT, 256, smemA>>>(x, emb, bih);
    k_rnn<<<NB, 128, smemB>>>(Whh, bhh);
    k_fc<<<1, 512>>>(Wfc, bfc, out);
}

// round 2
// speedup vs baseline: 2.1124x; 2.1124x over previous
#include <cuda_runtime.h>
#include <cstdint>
#include <cstddef>

#define BB 64
#define TT 512
#define EE 300
#define HH 1024
#define GG 3072   // 3*HH
#define OO 5

#define NB 128    // blocks in persistent recurrent kernel (1 per SM)
#define JPB 8     // HH / NB hidden units per block
#define THR 256   // threads in k_rnn
#define KC 64     // h chunk staged per sync

// ---------------- device scratch ----------------
__device__ float g_gx[(size_t)TT * GG * BB];   // [t][g][b]
__device__ float g_WT[EE * GG];                // W_ih transposed: [e][g]
__device__ float g_h[2][HH * BB];              // hidden double buffer, [j][b]
__device__ unsigned g_arrive;

// ---------------- f32x2 helpers (sm_103a packed fp32) ----------------
__device__ __forceinline__ void fma2(uint64_t& a, uint64_t b, uint64_t c) {
    asm("fma.rn.f32x2 %0, %1, %2, %0;" : "+l"(a) : "l"(b), "l"(c));
}
__device__ __forceinline__ uint64_t dup2(float x) {
    uint64_t r; asm("mov.b64 %0, {%1, %1};" : "=l"(r) : "f"(x)); return r;
}
__device__ __forceinline__ void unpk(uint64_t v, float& lo, float& hi) {
    asm("mov.b64 {%0, %1}, %2;" : "=f"(lo), "=f"(hi) : "l"(v));
}

// ---------------- tiny helpers ----------------
__global__ void k_reset() { g_arrive = 0u; }

__global__ void k_transpose(const float* __restrict__ Wih) {
    int i = blockIdx.x * blockDim.x + threadIdx.x;
    if (i < EE * GG) {
        int e = i / GG, g = i - e * GG;
        g_WT[i] = Wih[(size_t)g * EE + e];
    }
}

// ---------------- kernel A: gx[t][g][b] ----------------
// one block per t; tile per thread: 2b x 8j, acc packed over j-pairs (FFMA2).
__global__ void __launch_bounds__(256) k_gx(const int* __restrict__ x,
                                            const float* __restrict__ emb,
                                            const float* __restrict__ bih) {
    extern __shared__ float sm[];
    float* embS = sm;            // [e][b]
    float* Wt   = sm + EE * BB;  // [e][64] current g-tile

    const int t   = blockIdx.x;
    const int tid = threadIdx.x;

    for (int i = tid; i < BB * EE; i += 256) {
        int b = i / EE, e = i - b * EE;
        embS[e * BB + b] = emb[(size_t)x[b * TT + t] * EE + e];
    }

    const int bg = tid & 31;   // b-pair
    const int gy = tid >> 5;   // 0..7: 8 g's per tile

    for (int gt = 0; gt < GG / 64; gt++) {
        __syncthreads();
        for (int i = tid; i < EE * 64; i += 256) {
            int e = i >> 6, g = i & 63;
            Wt[i] = g_WT[e * GG + gt * 64 + g];
        }
        __syncthreads();

        uint64_t a0[4], a1[4];
        uint64_t z0 = dup2(0.f);
#pragma unroll
        for (int p = 0; p < 4; p++) { a0[p] = z0; a1[p] = z0; }

#pragma unroll 4
        for (int e = 0; e < EE; e++) {
            float2 eb = *(float2*)&embS[e * BB + bg * 2];
            uint64_t e0 = dup2(eb.x), e1 = dup2(eb.y);
            const uint64_t* wr = (const uint64_t*)&Wt[e * 64 + gy * 8];
#pragma unroll
            for (int p = 0; p < 4; p++) {
                uint64_t w = wr[p];
                fma2(a0[p], w, e0);
                fma2(a1[p], w, e1);
            }
        }
#pragma unroll
        for (int p = 0; p < 4; p++) {
            int j = gt * 64 + gy * 8 + 2 * p;
            float l0, h0, l1, h1;
            unpk(a0[p], l0, h0);
            unpk(a1[p], l1, h1);
            float bj = bih[j], bk = bih[j + 1];
            size_t base = ((size_t)t * GG + j) * BB + bg * 2;
            g_gx[base]          = l0 + bj;
            g_gx[base + 1]      = l1 + bj;
            g_gx[base + BB]     = h0 + bk;
            g_gx[base + BB + 1] = h1 + bk;
        }
    }
}

// ---------------- grid-wide spin barrier ----------------
__device__ __forceinline__ void gridbar(unsigned target) {
    __threadfence();
    __syncthreads();
    if (threadIdx.x == 0) {
        atomicAdd(&g_arrive, 1u);
        unsigned v;
        do {
            asm volatile("ld.global.acquire.gpu.u32 %0, [%1];"
                         : "=r"(v) : "l"(&g_arrive) : "memory");
        } while (v < target);
    }
    __syncthreads();
}

__device__ __forceinline__ float sigf(float v) { return 1.0f / (1.0f + expf(-v)); }

// ---------------- kernel B: persistent GRU recurrence ----------------
// 256 thr = 8 bg (8 b's each) x 4 jg (j-pair each) x 8 ks (k-split, = warp id).
// Acc: [3 gates][8 b] packed f32x2 over j-pair. W slice in smem all 512 steps.
__global__ void __launch_bounds__(THR, 1) k_rnn(const float* __restrict__ Whh,
                                                const float* __restrict__ bhh) {
    extern __shared__ float sm[];
    float* Wsm  = sm;                  // [3][1024][8]  = 24576 floats (96 KB)
    float* hs   = sm + 24576;          // 2 x [KC][64]  = 8192 floats  (32 KB)
    float* part = sm + 24576 + 8192;   // 12288 floats  (48 KB)

    const int tid = threadIdx.x;
    const int bg  = tid & 7;           // 8 b's: b = bg*8 .. bg*8+7
    const int jg  = (tid >> 3) & 3;    // j-pair: jl = jg*2, jg*2+1
    const int ks  = tid >> 5;          // k-split = warp id (uniform per warp)
    const int jbase = blockIdx.x * JPB;

    // load W_hh slice: Wsm[(g*1024 + k)*8 + jl] = Whh[(g*HH + jbase + jl)*HH + k]
    for (int i = tid; i < 3 * HH * JPB; i += THR) {
        int jl = i & 7;
        int k  = (i >> 3) & (HH - 1);
        int g  = i >> 13;
        Wsm[i] = Whh[((size_t)(g * HH + jbase + jl)) * HH + k];
    }

    // consumer-role constants: thread handles (jl_c, b0_c, b0_c+1)
    const int jl_c = tid >> 5;         // 0..7
    const int bp_c = tid & 31;
    const int b0   = bp_c * 2;
    const int jglob = jbase + jl_c;
    const float br = bhh[jglob];
    const float bz = bhh[HH + jglob];
    const float bn = bhh[2 * HH + jglob];
    const int bgc = b0 >> 3, lb0 = b0 & 7;  // lb0 even, lb0+1 same bg

    // zero h buffer 0 (our slice)
    for (int i = tid; i < JPB * BB; i += THR)
        __stcg(&g_h[0][jbase * BB + i], 0.f);

    unsigned tgt = NB;
    gridbar(tgt);

    const uint64_t zz = dup2(0.f);

    for (int t = 0; t < TT; t++) {
        const float* hin  = g_h[t & 1];
        float*       hout = g_h[(t + 1) & 1];

        // prefetch this thread's gate operands (consumed after reduction)
        const float* gxt = g_gx + (size_t)t * GG * BB;
        float2 pxr = __ldcg((const float2*)&gxt[(0 * HH + jglob) * BB + b0]);
        float2 pxz = __ldcg((const float2*)&gxt[(1 * HH + jglob) * BB + b0]);
        float2 pxn = __ldcg((const float2*)&gxt[(2 * HH + jglob) * BB + b0]);
        float2 ph  = __ldcg((const float2*)&hin[jglob * BB + b0]);

        uint64_t accR[8], accZ[8], accN[8];
#pragma unroll
        for (int b = 0; b < 8; b++) { accR[b] = zz; accZ[b] = zz; accN[b] = zz; }

        // stage chunk 0
        {
            const float4* src = (const float4*)&hin[0];
            float4* dst = (float4*)&hs[0];
#pragma unroll
            for (int i = 0; i < 4; i++) {
                float4 v = __ldcg(&src[tid + THR * i]);
                dst[tid + THR * i] = v;
            }
        }
        __syncthreads();

        for (int c = 0; c < HH / KC; c++) {
            // prefetch next chunk into regs
            float4 q[4];
            if (c < HH / KC - 1) {
                const float4* src = (const float4*)&hin[(c + 1) * KC * BB];
#pragma unroll
                for (int i = 0; i < 4; i++) q[i] = __ldcg(&src[tid + THR * i]);
            }

            const float* hb = hs + (c & 1) * (KC * BB);
#pragma unroll
            for (int i = 0; i < 8; i++) {
                int kk = ks + 8 * i;          // all lanes of a warp share kk
                int k  = c * KC + kk;
                const float* hr = &hb[kk * BB + bg * 8];
                float4 ha = *(const float4*)hr;
                float4 hc = *(const float4*)(hr + 4);
                uint64_t d0 = dup2(ha.x), d1 = dup2(ha.y), d2 = dup2(ha.z), d3 = dup2(ha.w);
                uint64_t d4 = dup2(hc.x), d5 = dup2(hc.y), d6 = dup2(hc.z), d7 = dup2(hc.w);
                uint64_t wr = *(const uint64_t*)&Wsm[(0 * HH + k) * 8 + jg * 2];
                uint64_t wz = *(const uint64_t*)&Wsm[(1 * HH + k) * 8 + jg * 2];
                uint64_t wn = *(const uint64_t*)&Wsm[(2 * HH + k) * 8 + jg * 2];
                fma2(accR[0], wr, d0); fma2(accR[1], wr, d1); fma2(accR[2], wr, d2); fma2(accR[3], wr, d3);
                fma2(accR[4], wr, d4); fma2(accR[5], wr, d5); fma2(accR[6], wr, d6); fma2(accR[7], wr, d7);
                fma2(accZ[0], wz, d0); fma2(accZ[1], wz, d1); fma2(accZ[2], wz, d2); fma2(accZ[3], wz, d3);
                fma2(accZ[4], wz, d4); fma2(accZ[5], wz, d5); fma2(accZ[6], wz, d6); fma2(accZ[7], wz, d7);
                fma2(accN[0], wn, d0); fma2(accN[1], wn, d1); fma2(accN[2], wn, d2); fma2(accN[3], wn, d3);
                fma2(accN[4], wn, d4); fma2(accN[5], wn, d5); fma2(accN[6], wn, d6); fma2(accN[7], wn, d7);
            }

            if (c < HH / KC - 1) {
                float4* dst = (float4*)&hs[((c + 1) & 1) * (KC * BB)];
#pragma unroll
                for (int i = 0; i < 4; i++) dst[tid + THR * i] = q[i];
            }
            __syncthreads();
        }

        // ---- reduction over ks via smem ----
        // layout: part_u64[ ((ks*3+g)*8 + lb)*4 + jg )*8 + bg ]
        {
            uint64_t* pp = (uint64_t*)part;
#pragma unroll
            for (int b = 0; b < 8; b++) {
                int base = (((ks * 3 + 0) * 8 + b) * 4 + jg) * 8 + bg;
                pp[base] = accR[b];
                pp[(((ks * 3 + 1) * 8 + b) * 4 + jg) * 8 + bg] = accZ[b];
                pp[(((ks * 3 + 2) * 8 + b) * 4 + jg) * 8 + bg] = accN[b];
            }
        }
        __syncthreads();

        float sR0 = 0.f, sR1 = 0.f, sZ0 = 0.f, sZ1 = 0.f, sN0 = 0.f, sN1 = 0.f;
        {
            const float* pf = part;
            const int jgc = jl_c >> 1, par = jl_c & 1;
#pragma unroll
            for (int s = 0; s < 8; s++) {
                int i0 = ((((s * 3 + 0) * 8 + lb0) * 4 + jgc) * 8 + bgc) * 2 + par;
                int i1 = ((((s * 3 + 0) * 8 + lb0 + 1) * 4 + jgc) * 8 + bgc) * 2 + par;
                sR0 += pf[i0]; sR1 += pf[i1];
                int z0i = ((((s * 3 + 1) * 8 + lb0) * 4 + jgc) * 8 + bgc) * 2 + par;
                int z1i = ((((s * 3 + 1) * 8 + lb0 + 1) * 4 + jgc) * 8 + bgc) * 2 + par;
                sZ0 += pf[z0i]; sZ1 += pf[z1i];
                int n0i = ((((s * 3 + 2) * 8 + lb0) * 4 + jgc) * 8 + bgc) * 2 + par;
                int n1i = ((((s * 3 + 2) * 8 + lb0 + 1) * 4 + jgc) * 8 + bgc) * 2 + par;
                sN0 += pf[n0i]; sN1 += pf[n1i];
            }
        }

        // ---- gates ----
        {
            float r, z, n;
            float2 o;
            r = sigf(pxr.x + sR0 + br);
            z = sigf(pxz.x + sZ0 + bz);
            n = tanhf(pxn.x + r * (sN0 + bn));
            o.x = (1.f - z) * n + z * ph.x;
            r = sigf(pxr.y + sR1 + br);
            z = sigf(pxz.y + sZ1 + bz);
            n = tanhf(pxn.y + r * (sN1 + bn));
            o.y = (1.f - z) * n + z * ph.y;
            __stcg((float2*)&hout[jglob * BB + b0], o);
        }

        tgt += NB;
        gridbar(tgt);
    }
}

// ---------------- kernel C: FC ----------------
__global__ void k_fc(const float* __restrict__ Wfc, const float* __restrict__ bfc,
                     float* __restrict__ out) {
    int tid = threadIdx.x;
    if (tid >= BB * OO) return;
    int b = tid & 63, o = tid >> 6;
    const float* h = g_h[0];   // TT even -> final state in buffer 0
    float a0 = 0.f, a1 = 0.f, a2 = 0.f, a3 = 0.f;
    for (int j = 0; j < HH; j += 4) {
        a0 += h[(j + 0) * BB + b] * Wfc[o * HH + j + 0];
        a1 += h[(j + 1) * BB + b] * Wfc[o * HH + j + 1];
        a2 += h[(j + 2) * BB + b] * Wfc[o * HH + j + 2];
        a3 += h[(j + 3) * BB + b] * Wfc[o * HH + j + 3];
    }
    out[b * OO + o] = a0 + a1 + a2 + a3 + bfc[o];
}

// ---------------- entry ----------------
extern "C" void kernel_launch(void* const* d_in, const int* in_sizes, int n_in,
                              void* d_out, int out_size) {
    const int*   x   = (const int*)d_in[0];
    const float* emb = (const float*)d_in[1];
    const float* Wih = (const float*)d_in[2];
    const float* Whh = (const float*)d_in[3];
    const float* bih = (const float*)d_in[4];
    const float* bhh = (const float*)d_in[5];
    const float* Wfc = (const float*)d_in[6];
    const float* bfc = (const float*)d_in[7];
    float* out = (float*)d_out;

    const int smemA = 2 * EE * BB * (int)sizeof(float);                 // 153.6 KB
    const int smemB = (24576 + 8192 + 12288) * (int)sizeof(float);      // 176 KB
    cudaFuncSetAttribute(k_gx,  cudaFuncAttributeMaxDynamicSharedMemorySize, smemA);
    cudaFuncSetAttribute(k_rnn, cudaFuncAttributeMaxDynamicSharedMemorySize, smemB);

    k_reset<<<1, 1>>>();
    k_transpose<<<(EE * GG + 255) / 256, 256>>>(Wih);
    k_gx<<<TT, 256, smemA>>>(x, emb, bih);
    k_rnn<<<NB, THR, smemB>>>(Whh, bhh);
    k_fc<<<1, 512>>>(Wfc, bfc, out);
}

// round 3
// speedup vs baseline: 2.2063x; 1.0445x over previous
#include <cuda_runtime.h>
#include <cstdint>
#include <cstddef>

#define BB 64
#define TT 512
#define EE 300
#define HH 1024
#define GG 3072   // 3*HH
#define OO 5

#define NB 128    // blocks in persistent recurrent kernel (1 per SM)
#define JPB 8     // HH / NB hidden units per block
#define THR 512   // threads in k_rnn: 16 warps = 16-way k-split

// ---------------- device scratch ----------------
__device__ float g_gx[(size_t)TT * GG * BB];   // [t][g][b]
__device__ float g_WT[EE * GG];                // W_ih transposed: [e][g]
__device__ float g_h[2][HH * BB];              // hidden double buffer, [j][b]
__device__ unsigned g_flags[NB * 32];          // per-block barrier flags, 128B stride

// ---------------- f32x2 helpers (sm_103a packed fp32) ----------------
__device__ __forceinline__ void fma2(uint64_t& a, uint64_t b, uint64_t c) {
    asm("fma.rn.f32x2 %0, %1, %2, %0;" : "+l"(a) : "l"(b), "l"(c));
}
__device__ __forceinline__ uint64_t dup2(float x) {
    uint64_t r; asm("mov.b64 %0, {%1, %1};" : "=l"(r) : "f"(x)); return r;
}
__device__ __forceinline__ void unpk(uint64_t v, float& lo, float& hi) {
    asm("mov.b64 {%0, %1}, %2;" : "=f"(lo), "=f"(hi) : "l"(v));
}
__device__ __forceinline__ uint32_t smem_u32(const void* p) {
    uint32_t a;
    asm("{ .reg .u64 t; cvta.to.shared.u64 t, %1; cvt.u32.u64 %0, t; }" : "=r"(a) : "l"(p));
    return a;
}
__device__ __forceinline__ void cpa16(uint32_t dst, const void* src) {
    asm volatile("cp.async.cg.shared.global [%0], [%1], 16;" :: "r"(dst), "l"(src));
}
#define CP_COMMIT() asm volatile("cp.async.commit_group;" ::: "memory")
#define CP_WAIT0()  asm volatile("cp.async.wait_group 0;" ::: "memory")

// ---------------- tiny helpers ----------------
__global__ void k_reset() { if (threadIdx.x < NB) g_flags[threadIdx.x * 32] = 0u; }

__global__ void k_transpose(const float* __restrict__ Wih) {
    int i = blockIdx.x * blockDim.x + threadIdx.x;
    if (i < EE * GG) {
        int e = i / GG, g = i - e * GG;
        g_WT[i] = Wih[(size_t)g * EE + e];
    }
}

// ---------------- kernel A: gx[t][g][b] ----------------
__global__ void __launch_bounds__(256) k_gx(const int* __restrict__ x,
                                            const float* __restrict__ emb,
                                            const float* __restrict__ bih) {
    extern __shared__ float sm[];
    float* embS = sm;            // [e][b]
    float* Wt   = sm + EE * BB;  // [e][64] current g-tile

    const int t   = blockIdx.x;
    const int tid = threadIdx.x;

    for (int i = tid; i < BB * EE; i += 256) {
        int b = i / EE, e = i - b * EE;
        embS[e * BB + b] = emb[(size_t)x[b * TT + t] * EE + e];
    }

    const int bg = tid & 31;
    const int gy = tid >> 5;

    for (int gt = 0; gt < GG / 64; gt++) {
        __syncthreads();
        for (int i = tid; i < EE * 64; i += 256) {
            int e = i >> 6, g = i & 63;
            Wt[i] = g_WT[e * GG + gt * 64 + g];
        }
        __syncthreads();

        uint64_t a0[4], a1[4];
        uint64_t z0 = dup2(0.f);
#pragma unroll
        for (int p = 0; p < 4; p++) { a0[p] = z0; a1[p] = z0; }

#pragma unroll 4
        for (int e = 0; e < EE; e++) {
            float2 eb = *(float2*)&embS[e * BB + bg * 2];
            uint64_t e0 = dup2(eb.x), e1 = dup2(eb.y);
            const uint64_t* wr = (const uint64_t*)&Wt[e * 64 + gy * 8];
#pragma unroll
            for (int p = 0; p < 4; p++) {
                uint64_t w = wr[p];
                fma2(a0[p], w, e0);
                fma2(a1[p], w, e1);
            }
        }
#pragma unroll
        for (int p = 0; p < 4; p++) {
            int j = gt * 64 + gy * 8 + 2 * p;
            float l0, h0, l1, h1;
            unpk(a0[p], l0, h0);
            unpk(a1[p], l1, h1);
            float bj = bih[j], bk = bih[j + 1];
            size_t base = ((size_t)t * GG + j) * BB + bg * 2;
            g_gx[base]          = l0 + bj;
            g_gx[base + 1]      = l1 + bj;
            g_gx[base + BB]     = h0 + bk;
            g_gx[base + BB + 1] = h1 + bk;
        }
    }
}

// ---------------- flag-based grid barrier ----------------
__device__ __forceinline__ void gridbar(unsigned tgt) {
    __threadfence();
    __syncthreads();
    if (threadIdx.x == 0)
        asm volatile("st.global.release.gpu.u32 [%0], %1;"
                     :: "l"(&g_flags[blockIdx.x * 32]), "r"(tgt) : "memory");
    if (threadIdx.x < NB) {
        unsigned v;
        do {
            asm volatile("ld.global.acquire.gpu.u32 %0, [%1];"
                         : "=r"(v) : "l"(&g_flags[threadIdx.x * 32]) : "memory");
        } while (v < tgt);
    }
    __syncthreads();
}

__device__ __forceinline__ float sigf(float v) { return 1.0f / (1.0f + expf(-v)); }

// ---------------- kernel B: persistent GRU recurrence ----------------
// 512 thr = 16 warps. Warp w owns k in [w*64, w*64+64), stages its own h chunks
// (cp.async double-buffer, warp-private -> no block syncs in k-loop).
// Lane: bg = lane&7 (8 b's), jg = lane>>3 (j-pair). Acc: [3 gates][8 b] f32x2 over j-pair.
__global__ void __launch_bounds__(THR, 1) k_rnn(const float* __restrict__ Whh,
                                                const float* __restrict__ bhh) {
    extern __shared__ float sm[];
    float* Wsm     = sm;                 // [3][1024][8]  = 24576 floats (96 KB)
    float* scratch = sm + 24576;         // 24576 floats (96 KB): hs (first 16K) U part
    uint64_t* part = (uint64_t*)scratch; // 12288 u64

    const int tid  = threadIdx.x;
    const int w    = tid >> 5, lane = tid & 31;
    const int bg   = lane & 7, jg = lane >> 3;
    const int jbase = blockIdx.x * JPB;

    // load W_hh slice once: Wsm[(g*1024+k)*8 + jl]
    for (int i = tid; i < 3 * HH * JPB; i += THR) {
        int jl = i & 7, k = (i >> 3) & (HH - 1), g = i >> 13;
        Wsm[i] = Whh[((size_t)(g * HH + jbase + jl)) * HH + k];
    }

    // consumer role (tid < 256): handles (j-pair cjg, batch cb)
    const int cjg = (tid >> 6) & 3;
    const int cb  = tid & 63;
    const int cbg = cb >> 3, cbi = cb & 7;
    const int j0 = jbase + cjg * 2, j1 = j0 + 1;
    const float br0 = bhh[j0],          br1 = bhh[j1];
    const float bz0 = bhh[HH + j0],     bz1 = bhh[HH + j1];
    const float bn0 = bhh[2 * HH + j0], bn1 = bhh[2 * HH + j1];
    const bool consumer = (tid < 256);

    // zero h buffer 0 (our slice)
    for (int i = tid; i < JPB * BB; i += THR)
        __stcg(&g_h[0][jbase * BB + i], 0.f);

    gridbar(1);

    float* hw = scratch + w * 1024;              // warp-private [2][512] floats
    const uint32_t hw32 = smem_u32(hw);
    const uint64_t zz = dup2(0.f);

    for (int t = 0; t < TT; t++) {
        const float* hin  = g_h[t & 1];
        float*       hout = g_h[(t + 1) & 1];

        // prefetch gate operands (consumers only; warp-uniform branch)
        float xr0, xr1, xz0, xz1, xn0, xn1, hp0, hp1;
        if (consumer) {
            const float* gxt = g_gx + (size_t)t * GG * BB;
            xr0 = __ldcg(&gxt[(0 * HH + j0) * BB + cb]);
            xr1 = __ldcg(&gxt[(0 * HH + j1) * BB + cb]);
            xz0 = __ldcg(&gxt[(1 * HH + j0) * BB + cb]);
            xz1 = __ldcg(&gxt[(1 * HH + j1) * BB + cb]);
            xn0 = __ldcg(&gxt[(2 * HH + j0) * BB + cb]);
            xn1 = __ldcg(&gxt[(2 * HH + j1) * BB + cb]);
            hp0 = __ldcg(&hin[j0 * BB + cb]);
            hp1 = __ldcg(&hin[j1 * BB + cb]);
        }

        uint64_t aR[8], aZ[8], aN[8];
#pragma unroll
        for (int b = 0; b < 8; b++) { aR[b] = zz; aZ[b] = zz; aN[b] = zz; }

        // ---- warp-private staged k-loop, cp.async double buffer ----
        const char* src = (const char*)(hin + w * 64 * BB);  // warp's 64-k range (16 KB)
#pragma unroll
        for (int i = 0; i < 4; i++)
            cpa16(hw32 + lane * 16 + i * 512, src + lane * 16 + i * 512);
        CP_COMMIT(); CP_WAIT0();
        __syncwarp();

        for (int c = 0; c < 8; c++) {
            if (c < 7) {
#pragma unroll
                for (int i = 0; i < 4; i++)
                    cpa16(hw32 + (((c + 1) & 1) * 2048) + lane * 16 + i * 512,
                          src + (c + 1) * 2048 + lane * 16 + i * 512);
                CP_COMMIT();
            }
            const float* hb = hw + (c & 1) * 512;
            const int kb = w * 64 + c * 8;
#pragma unroll
            for (int k2 = 0; k2 < 8; k2++) {
                const int k = kb + k2;
                float4 ha = *(const float4*)&hb[k2 * 64 + bg * 8];
                float4 hc = *(const float4*)&hb[k2 * 64 + bg * 8 + 4];
                uint64_t wr  = *(const uint64_t*)&Wsm[(0 * HH + k) * 8 + jg * 2];
                uint64_t wz2 = *(const uint64_t*)&Wsm[(1 * HH + k) * 8 + jg * 2];
                uint64_t wn2 = *(const uint64_t*)&Wsm[(2 * HH + k) * 8 + jg * 2];
                uint64_t d0 = dup2(ha.x), d1 = dup2(ha.y), d2 = dup2(ha.z), d3 = dup2(ha.w);
                uint64_t d4 = dup2(hc.x), d5 = dup2(hc.y), d6 = dup2(hc.z), d7 = dup2(hc.w);
                fma2(aR[0], wr, d0);  fma2(aR[1], wr, d1);  fma2(aR[2], wr, d2);  fma2(aR[3], wr, d3);
                fma2(aR[4], wr, d4);  fma2(aR[5], wr, d5);  fma2(aR[6], wr, d6);  fma2(aR[7], wr, d7);
                fma2(aZ[0], wz2, d0); fma2(aZ[1], wz2, d1); fma2(aZ[2], wz2, d2); fma2(aZ[3], wz2, d3);
                fma2(aZ[4], wz2, d4); fma2(aZ[5], wz2, d5); fma2(aZ[6], wz2, d6); fma2(aZ[7], wz2, d7);
                fma2(aN[0], wn2, d0); fma2(aN[1], wn2, d1); fma2(aN[2], wn2, d2); fma2(aN[3], wn2, d3);
                fma2(aN[4], wn2, d4); fma2(aN[5], wn2, d5); fma2(aN[6], wn2, d6); fma2(aN[7], wn2, d7);
            }
            if (c < 7) CP_WAIT0();
            __syncwarp();
        }

        // ---- 16-way k-split reduction (part aliases staging; safe after barrier) ----
        __syncthreads();
#pragma unroll
        for (int bi = 0; bi < 8; bi++) {
            int col = ((jg * 8 + bg) + bi * 8) & 31;   // swizzle: 2-wavefront STS, <=2-way LDS
            part[(w * 3 + 0) * 256 + bi * 32 + col] = aR[bi];
            part[(w * 3 + 1) * 256 + bi * 32 + col] = aZ[bi];
            part[(w * 3 + 2) * 256 + bi * 32 + col] = aN[bi];
        }
        __syncthreads();

        if (consumer) {
            float sR0 = 0.f, sR1 = 0.f, sZ0 = 0.f, sZ1 = 0.f, sN0 = 0.f, sN1 = 0.f;
            const int ccol = ((cjg * 8 + cbg) + cbi * 8) & 31;
#pragma unroll
            for (int s = 0; s < 16; s++) {
                float2 vr = *(const float2*)&part[(s * 3 + 0) * 256 + cbi * 32 + ccol];
                float2 vz = *(const float2*)&part[(s * 3 + 1) * 256 + cbi * 32 + ccol];
                float2 vn = *(const float2*)&part[(s * 3 + 2) * 256 + cbi * 32 + ccol];
                sR0 += vr.x; sR1 += vr.y;
                sZ0 += vz.x; sZ1 += vz.y;
                sN0 += vn.x; sN1 += vn.y;
            }
            float r, z, n;
            r = sigf(xr0 + sR0 + br0);
            z = sigf(xz0 + sZ0 + bz0);
            n = tanhf(xn0 + r * (sN0 + bn0));
            __stcg(&hout[j0 * BB + cb], (1.f - z) * n + z * hp0);
            r = sigf(xr1 + sR1 + br1);
            z = sigf(xz1 + sZ1 + bz1);
            n = tanhf(xn1 + r * (sN1 + bn1));
            __stcg(&hout[j1 * BB + cb], (1.f - z) * n + z * hp1);
        }

        gridbar((unsigned)(t + 2));
    }
}

// ---------------- kernel C: FC ----------------
__global__ void k_fc(const float* __restrict__ Wfc, const float* __restrict__ bfc,
                     float* __restrict__ out) {
    int tid = threadIdx.x;
    if (tid >= BB * OO) return;
    int b = tid & 63, o = tid >> 6;
    const float* h = g_h[0];   // TT even -> final state in buffer 0
    float a0 = 0.f, a1 = 0.f, a2 = 0.f, a3 = 0.f;
    for (int j = 0; j < HH; j += 4) {
        a0 += h[(j + 0) * BB + b] * Wfc[o * HH + j + 0];
        a1 += h[(j + 1) * BB + b] * Wfc[o * HH + j + 1];
        a2 += h[(j + 2) * BB + b] * Wfc[o * HH + j + 2];
        a3 += h[(j + 3) * BB + b] * Wfc[o * HH + j + 3];
    }
    out[b * OO + o] = a0 + a1 + a2 + a3 + bfc[o];
}

// ---------------- entry ----------------
extern "C" void kernel_launch(void* const* d_in, const int* in_sizes, int n_in,
                              void* d_out, int out_size) {
    const int*   x   = (const int*)d_in[0];
    const float* emb = (const float*)d_in[1];
    const float* Wih = (const float*)d_in[2];
    const float* Whh = (const float*)d_in[3];
    const float* bih = (const float*)d_in[4];
    const float* bhh = (const float*)d_in[5];
    const float* Wfc = (const float*)d_in[6];
    const float* bfc = (const float*)d_in[7];
    float* out = (float*)d_out;

    const int smemA = 2 * EE * BB * (int)sizeof(float);          // 153.6 KB
    const int smemB = (24576 + 24576) * (int)sizeof(float);      // 192 KB
    cudaFuncSetAttribute(k_gx,  cudaFuncAttributeMaxDynamicSharedMemorySize, smemA);
    cudaFuncSetAttribute(k_rnn, cudaFuncAttributeMaxDynamicSharedMemorySize, smemB);

    k_reset<<<1, 128>>>();
    k_transpose<<<(EE * GG + 255) / 256, 256>>>(Wih);
    k_gx<<<TT, 256, smemA>>>(x, emb, bih);
    k_rnn<<<NB, THR, smemB>>>(Whh, bhh);
    k_fc<<<1, 512>>>(Wfc, bfc, out);
}